// round 8
// baseline (speedup 1.0000x reference)
#include <cuda_runtime.h>
#include <cuda_fp16.h>
#include <cstdint>

// Problem constants
#define B_    2
#define S_    512
#define D_    512
#define MTOK  1024          // B*S tokens
#define NTOT  1536          // w1 | w2 | w3
#define EPS_  1e-5f

// Static device scratch
__device__ float  g_P[MTOK * NTOT];     // 6 MB projections
__device__ __half g_A0[MTOK * D_];      // X hi (rounded) split
__device__ __half g_A1[MTOK * D_];      // X lo split
__device__ __half g_B0[NTOT * D_];      // W concat hi split
__device__ __half g_B1[NTOT * D_];      // W concat lo split

// ---------------------------------------------------------------------------
// Kernel 0: split fp32 -> fp16 hi/lo. 8 floats/thread (R6 version).
// ---------------------------------------------------------------------------
#define XFL   (MTOK * D_)              // 524288 floats in X
#define TOTG  ((MTOK + NTOT) * D_ / 8) // 163840 groups of 8

__global__ __launch_bounds__(256) void split_kernel(
    const float* __restrict__ X,
    const float* __restrict__ Win,
    const float* __restrict__ Wout,
    const float* __restrict__ Wb)
{
    const int g = blockIdx.x * 256 + threadIdx.x;
    if (g >= TOTG) return;
    const int q = g * 8;

    const float* src;
    __half *d0, *d1;
    if (q < XFL) {
        src = X + q;
        d0 = g_A0 + q;  d1 = g_A1 + q;
    } else {
        const int wq = q - XFL;
        const int n  = wq >> 9;
        const int k  = wq & (D_ - 1);
        src = (n < D_ ? Win + n * D_
                      : (n < 2 * D_ ? Wout + (n - D_) * D_
                                    : Wb + (n - 2 * D_) * D_)) + k;
        d0 = g_B0 + wq;  d1 = g_B1 + wq;
    }
    const float4 v0 = reinterpret_cast<const float4*>(src)[0];
    const float4 v1 = reinterpret_cast<const float4*>(src)[1];
    float f[8] = {v0.x, v0.y, v0.z, v0.w, v1.x, v1.y, v1.z, v1.w};
    __half hi[8], lo[8];
    #pragma unroll
    for (int i = 0; i < 8; ++i) {
        hi[i] = __float2half_rn(f[i]);
        lo[i] = __float2half_rn(f[i] - __half2float(hi[i]));
    }
    uint4 sh, sl;
    sh.x = *(uint32_t*)&hi[0]; sh.y = *(uint32_t*)&hi[2];
    sh.z = *(uint32_t*)&hi[4]; sh.w = *(uint32_t*)&hi[6];
    sl.x = *(uint32_t*)&lo[0]; sl.y = *(uint32_t*)&lo[2];
    sl.z = *(uint32_t*)&lo[4]; sl.w = *(uint32_t*)&lo[6];
    *reinterpret_cast<uint4*>(d0) = sh;
    *reinterpret_cast<uint4*>(d1) = sl;
}

// ---------------------------------------------------------------------------
// Shared GEMM helpers
// ---------------------------------------------------------------------------
#define BK 32
#define KP 40     // halves per smem row: conflict-free fragment LDS

__device__ __forceinline__ void cp16(uint32_t smem, const void* gmem) {
    asm volatile("cp.async.cg.shared.global [%0], [%1], 16;\n"
                 :: "r"(smem), "l"(gmem));
}

__device__ __forceinline__ void mma_f16(float* c,
    uint32_t a0, uint32_t a1, uint32_t a2, uint32_t a3,
    uint32_t b0, uint32_t b1)
{
    asm volatile(
        "mma.sync.aligned.m16n8k16.row.col.f32.f16.f16.f32 "
        "{%0,%1,%2,%3}, {%4,%5,%6,%7}, {%8,%9}, {%0,%1,%2,%3};"
        : "+f"(c[0]), "+f"(c[1]), "+f"(c[2]), "+f"(c[3])
        : "r"(a0), "r"(a1), "r"(a2), "r"(a3), "r"(b0), "r"(b1));
}

// ---------------------------------------------------------------------------
// Kernel 1a: w1|w3 projections, 2-pass (A single-rounded fp16, B exact pair).
// BM=64 BN=128, grid 16x8 = 128 uniform CTAs. 8 warps: 2M x 4N, warp 32x32.
// ---------------------------------------------------------------------------
#define W13_A0  0
#define W13_B0  (64 * KP)                    // 2560
#define W13_B1  (64 * KP + 128 * KP)         // 7680
#define W13_SH  (64 * KP + 2 * 128 * KP)     // 12800 halves
#define W13_SM  (2 * W13_SH * 2)             // 51200 B

__global__ __launch_bounds__(256, 1) void gemm_w13()
{
    extern __shared__ __half sm[];
    const int tid   = threadIdx.x;
    const int lane  = tid & 31;
    const int wid   = tid >> 5;
    const int warpM = wid >> 2;         // 0..1
    const int warpN = wid & 3;          // 0..3
    const int gID   = lane >> 2;
    const int tIG   = lane & 3;
    const int m0    = blockIdx.x * 64;
    const int by    = blockIdx.y;
    const int n0    = (by < 4) ? by * 128 : 1024 + (by - 4) * 128;  // w1 | w3

    const uint32_t sbase = (uint32_t)__cvta_generic_to_shared(sm);

    float acc[2][4][4];
    #pragma unroll
    for (int i = 0; i < 2; i++)
        #pragma unroll
        for (int j = 0; j < 4; j++)
            #pragma unroll
            for (int q = 0; q < 4; q++) acc[i][j][q] = 0.f;

    auto issue = [&](int t, int stg) {
        const int k0 = t * BK;
        const uint32_t st = sbase + (uint32_t)(stg * W13_SH) * 2u;
        {   // A0: 64 rows x 4 chunks = 256 = 1/thread
            const int r = tid >> 2, qd = tid & 3;
            cp16(st + (uint32_t)(W13_A0 + r * KP + qd * 8) * 2u,
                 g_A0 + (m0 + r) * D_ + k0 + qd * 8);
        }
        #pragma unroll
        for (int it = 0; it < 2; ++it) {   // B0/B1: 128 rows x 4 = 512 chunks
            const int c = tid + it * 256;
            const int r = c >> 2, qd = c & 3;
            const uint32_t so = (uint32_t)(r * KP + qd * 8) * 2u;
            cp16(st + W13_B0 * 2u + so, g_B0 + (n0 + r) * D_ + k0 + qd * 8);
            cp16(st + W13_B1 * 2u + so, g_B1 + (n0 + r) * D_ + k0 + qd * 8);
        }
        asm volatile("cp.async.commit_group;");
    };

    auto compute = [&](int stg) {
        const __half* Ah = sm + stg * W13_SH + W13_A0;
        const __half* Bh = sm + stg * W13_SH + W13_B0;
        const __half* Bl = sm + stg * W13_SH + W13_B1;
        #pragma unroll
        for (int kk = 0; kk < BK; kk += 16) {
            uint32_t ah[2][4], bh[4][2], bl[4][2];
            #pragma unroll
            for (int i = 0; i < 2; ++i) {
                const int r = warpM * 32 + i * 16 + gID;
                const int c = kk + 2 * tIG;
                ah[i][0] = *(const uint32_t*)&Ah[r * KP + c];
                ah[i][1] = *(const uint32_t*)&Ah[(r + 8) * KP + c];
                ah[i][2] = *(const uint32_t*)&Ah[r * KP + c + 8];
                ah[i][3] = *(const uint32_t*)&Ah[(r + 8) * KP + c + 8];
            }
            #pragma unroll
            for (int j = 0; j < 4; ++j) {
                const int n = warpN * 32 + j * 8 + gID;
                const int c = kk + 2 * tIG;
                bh[j][0] = *(const uint32_t*)&Bh[n * KP + c];
                bh[j][1] = *(const uint32_t*)&Bh[n * KP + c + 8];
                bl[j][0] = *(const uint32_t*)&Bl[n * KP + c];
                bl[j][1] = *(const uint32_t*)&Bl[n * KP + c + 8];
            }
            #pragma unroll
            for (int i = 0; i < 2; ++i)
                #pragma unroll
                for (int j = 0; j < 4; ++j)
                    mma_f16(acc[i][j], ah[i][0], ah[i][1], ah[i][2], ah[i][3],
                            bl[j][0], bl[j][1]);                    // a*lo
            #pragma unroll
            for (int i = 0; i < 2; ++i)
                #pragma unroll
                for (int j = 0; j < 4; ++j)
                    mma_f16(acc[i][j], ah[i][0], ah[i][1], ah[i][2], ah[i][3],
                            bh[j][0], bh[j][1]);                    // a*hi
        }
    };

    constexpr int T = D_ / BK;   // 16
    issue(0, 0);
    #pragma unroll 1
    for (int t = 0; t < T; ++t) {
        if (t + 1 < T) {
            issue(t + 1, (t + 1) & 1);
            asm volatile("cp.async.wait_group 1;");
        } else {
            asm volatile("cp.async.wait_group 0;");
        }
        __syncthreads();
        compute(t & 1);
        __syncthreads();
    }

    #pragma unroll
    for (int i = 0; i < 2; ++i) {
        const int r = m0 + warpM * 32 + i * 16 + gID;
        #pragma unroll
        for (int j = 0; j < 4; ++j) {
            const int c = n0 + warpN * 32 + j * 8 + 2 * tIG;
            *reinterpret_cast<float2*>(&g_P[r * NTOT + c]) =
                make_float2(acc[i][j][0], acc[i][j][1]);
            *reinterpret_cast<float2*>(&g_P[(r + 8) * NTOT + c]) =
                make_float2(acc[i][j][2], acc[i][j][3]);
        }
    }
}

// ---------------------------------------------------------------------------
// Kernel 1b: w2 projection, 3-pass (full accuracy; feeds rsqrt(w2^2+eps)).
// BM=64 BN=64, grid 16x8 = 128 uniform CTAs. 8 warps: 2M x 4N, warp 32x16.
// ---------------------------------------------------------------------------
#define W2_A0  0
#define W2_A1  (64 * KP)                     // 2560
#define W2_B0  (2 * 64 * KP)                 // 5120
#define W2_B1  (3 * 64 * KP)                 // 7680
#define W2_SH  (4 * 64 * KP)                 // 10240 halves
#define W2_SM  (2 * W2_SH * 2)               // 40960 B

__global__ __launch_bounds__(256, 1) void gemm_w2()
{
    extern __shared__ __half sm[];
    const int tid   = threadIdx.x;
    const int lane  = tid & 31;
    const int wid   = tid >> 5;
    const int warpM = wid >> 2;         // 0..1
    const int warpN = wid & 3;          // 0..3
    const int gID   = lane >> 2;
    const int tIG   = lane & 3;
    const int m0    = blockIdx.x * 64;
    const int n0    = 512 + blockIdx.y * 64;   // w2 columns

    const uint32_t sbase = (uint32_t)__cvta_generic_to_shared(sm);

    float acc[2][2][4];
    #pragma unroll
    for (int i = 0; i < 2; i++)
        #pragma unroll
        for (int j = 0; j < 2; j++)
            #pragma unroll
            for (int q = 0; q < 4; q++) acc[i][j][q] = 0.f;

    auto issue = [&](int t, int stg) {
        const int k0 = t * BK;
        const uint32_t st = sbase + (uint32_t)(stg * W2_SH) * 2u;
        const int r = tid >> 2, qd = tid & 3;   // 256 chunks per array
        const uint32_t so = (uint32_t)(r * KP + qd * 8) * 2u;
        cp16(st + W2_A0 * 2u + so, g_A0 + (m0 + r) * D_ + k0 + qd * 8);
        cp16(st + W2_A1 * 2u + so, g_A1 + (m0 + r) * D_ + k0 + qd * 8);
        cp16(st + W2_B0 * 2u + so, g_B0 + (n0 + r) * D_ + k0 + qd * 8);
        cp16(st + W2_B1 * 2u + so, g_B1 + (n0 + r) * D_ + k0 + qd * 8);
        asm volatile("cp.async.commit_group;");
    };

    auto compute = [&](int stg) {
        const __half* Ah = sm + stg * W2_SH + W2_A0;
        const __half* Al = sm + stg * W2_SH + W2_A1;
        const __half* Bh = sm + stg * W2_SH + W2_B0;
        const __half* Bl = sm + stg * W2_SH + W2_B1;
        #pragma unroll
        for (int kk = 0; kk < BK; kk += 16) {
            uint32_t ah[2][4], al[2][4], bh[2][2], bl[2][2];
            #pragma unroll
            for (int i = 0; i < 2; ++i) {
                const int r = warpM * 32 + i * 16 + gID;
                const int c = kk + 2 * tIG;
                ah[i][0] = *(const uint32_t*)&Ah[r * KP + c];
                ah[i][1] = *(const uint32_t*)&Ah[(r + 8) * KP + c];
                ah[i][2] = *(const uint32_t*)&Ah[r * KP + c + 8];
                ah[i][3] = *(const uint32_t*)&Ah[(r + 8) * KP + c + 8];
                al[i][0] = *(const uint32_t*)&Al[r * KP + c];
                al[i][1] = *(const uint32_t*)&Al[(r + 8) * KP + c];
                al[i][2] = *(const uint32_t*)&Al[r * KP + c + 8];
                al[i][3] = *(const uint32_t*)&Al[(r + 8) * KP + c + 8];
            }
            #pragma unroll
            for (int j = 0; j < 2; ++j) {
                const int n = warpN * 16 + j * 8 + gID;
                const int c = kk + 2 * tIG;
                bh[j][0] = *(const uint32_t*)&Bh[n * KP + c];
                bh[j][1] = *(const uint32_t*)&Bh[n * KP + c + 8];
                bl[j][0] = *(const uint32_t*)&Bl[n * KP + c];
                bl[j][1] = *(const uint32_t*)&Bl[n * KP + c + 8];
            }
            #pragma unroll
            for (int i = 0; i < 2; ++i)
                #pragma unroll
                for (int j = 0; j < 2; ++j)
                    mma_f16(acc[i][j], ah[i][0], ah[i][1], ah[i][2], ah[i][3],
                            bl[j][0], bl[j][1]);                    // hi*lo
            #pragma unroll
            for (int i = 0; i < 2; ++i)
                #pragma unroll
                for (int j = 0; j < 2; ++j)
                    mma_f16(acc[i][j], al[i][0], al[i][1], al[i][2], al[i][3],
                            bh[j][0], bh[j][1]);                    // lo*hi
            #pragma unroll
            for (int i = 0; i < 2; ++i)
                #pragma unroll
                for (int j = 0; j < 2; ++j)
                    mma_f16(acc[i][j], ah[i][0], ah[i][1], ah[i][2], ah[i][3],
                            bh[j][0], bh[j][1]);                    // hi*hi
        }
    };

    constexpr int T = D_ / BK;   // 16
    issue(0, 0);
    #pragma unroll 1
    for (int t = 0; t < T; ++t) {
        if (t + 1 < T) {
            issue(t + 1, (t + 1) & 1);
            asm volatile("cp.async.wait_group 1;");
        } else {
            asm volatile("cp.async.wait_group 0;");
        }
        __syncthreads();
        compute(t & 1);
        __syncthreads();
    }

    #pragma unroll
    for (int i = 0; i < 2; ++i) {
        const int r = m0 + warpM * 32 + i * 16 + gID;
        #pragma unroll
        for (int j = 0; j < 2; ++j) {
            const int c = n0 + warpN * 16 + j * 8 + 2 * tIG;
            *reinterpret_cast<float2*>(&g_P[r * NTOT + c]) =
                make_float2(acc[i][j][0], acc[i][j][1]);
            *reinterpret_cast<float2*>(&g_P[(r + 8) * NTOT + c]) =
                make_float2(acc[i][j][2], acc[i][j][3]);
        }
    }
}

// ---------------------------------------------------------------------------
// Kernel 2: per-token closed-form epilogue (rank-1 LN collapse).
// ---------------------------------------------------------------------------
__global__ __launch_bounds__(128) void finalize_kernel(
    const float* __restrict__ X, float* __restrict__ Y)
{
    __shared__ float red[6][4];
    const int m   = blockIdx.x;
    const int tid = threadIdx.x;
    const float* x = X + m * D_;
    const float* p = g_P + m * NTOT;   // w1 | w2 | w3

    const float4 a4  = *reinterpret_cast<const float4*>(&p[4 * tid]);
    const float4 x4  = *reinterpret_cast<const float4*>(&x[4 * tid]);
    const float4 c4  = *reinterpret_cast<const float4*>(&p[2 * D_ + 4 * tid]);

    float sw1  = (a4.x + a4.y) + (a4.z + a4.w);
    float sw1q = (a4.x * a4.x + a4.y * a4.y) + (a4.z * a4.z + a4.w * a4.w);
    float sx   = (x4.x + x4.y) + (x4.z + x4.w);
    float sw1x = (a4.x * x4.x + a4.y * x4.y) + (a4.z * x4.z + a4.w * x4.w);
    float sw3  = (c4.x + c4.y) + (c4.z + c4.w);
    float sw3q = (c4.x * c4.x + c4.y * c4.y) + (c4.z * c4.z + c4.w * c4.w);

    #pragma unroll
    for (int o = 16; o; o >>= 1) {
        sw1  += __shfl_xor_sync(0xffffffffu, sw1,  o);
        sw1q += __shfl_xor_sync(0xffffffffu, sw1q, o);
        sx   += __shfl_xor_sync(0xffffffffu, sx,   o);
        sw1x += __shfl_xor_sync(0xffffffffu, sw1x, o);
        sw3  += __shfl_xor_sync(0xffffffffu, sw3,  o);
        sw3q += __shfl_xor_sync(0xffffffffu, sw3q, o);
    }
    const int warp = tid >> 5, lane = tid & 31;
    if (lane == 0) {
        red[0][warp] = sw1;  red[1][warp] = sw1q; red[2][warp] = sx;
        red[3][warp] = sw1x; red[4][warp] = sw3;  red[5][warp] = sw3q;
    }
    __syncthreads();

    float r[6];
    #pragma unroll
    for (int j = 0; j < 6; j++)
        r[j] = (red[j][0] + red[j][1]) + (red[j][2] + red[j][3]);

    const float invD = 1.0f / (float)D_;
    const float mu1  = r[0] * invD;
    const float var1 = fmaxf(r[1] * invD - mu1 * mu1, 0.f);
    const float s    = r[3] - mu1 * r[2];
    const float mu3  = r[4] * invD;
    const float var3 = fmaxf(r[5] * invD - mu3 * mu3, 0.f);
    const float inv3 = rsqrtf(var3 + EPS_);

    const float4 v4 = *reinterpret_cast<const float4*>(&p[D_ + 4 * tid]);
    float4 out;
    out.x = v4.x * s * rsqrtf(v4.x * v4.x * var1 + EPS_) + (c4.x - mu3) * inv3;
    out.y = v4.y * s * rsqrtf(v4.y * v4.y * var1 + EPS_) + (c4.y - mu3) * inv3;
    out.z = v4.z * s * rsqrtf(v4.z * v4.z * var1 + EPS_) + (c4.z - mu3) * inv3;
    out.w = v4.w * s * rsqrtf(v4.w * v4.w * var1 + EPS_) + (c4.w - mu3) * inv3;
    *reinterpret_cast<float4*>(&Y[m * D_ + 4 * tid]) = out;
}

// ---------------------------------------------------------------------------
extern "C" void kernel_launch(void* const* d_in, const int* in_sizes, int n_in,
                              void* d_out, int out_size)
{
    const float* X    = (const float*)d_in[0];
    const float* Win  = (const float*)d_in[1];
    const float* Wout = (const float*)d_in[2];
    const float* Wb   = (const float*)d_in[3];
    float* Y = (float*)d_out;

    cudaFuncSetAttribute(gemm_w13,
                         cudaFuncAttributeMaxDynamicSharedMemorySize, W13_SM);
    cudaFuncSetAttribute(gemm_w2,
                         cudaFuncAttributeMaxDynamicSharedMemorySize, W2_SM);

    split_kernel<<<(TOTG + 255) / 256, 256>>>(X, Win, Wout, Wb);
    gemm_w13<<<dim3(16, 8), 256, W13_SM>>>();
    gemm_w2<<<dim3(16, 8), 256, W2_SM>>>();
    finalize_kernel<<<MTOK, 128>>>(X, Y);
}

// round 9
// speedup vs baseline: 1.1484x; 1.1484x over previous
#include <cuda_runtime.h>
#include <cuda_fp16.h>
#include <cstdint>

// Problem constants
#define B_    2
#define S_    512
#define D_    512
#define MTOK  1024          // B*S tokens
#define NTOT  1536          // w1 | w2 | w3
#define EPS_  1e-5f

// Static device scratch
__device__ float  g_P[MTOK * NTOT];     // 6 MB projections (ORIGINAL col order)
__device__ __half g_A0[MTOK * D_];      // X hi split
__device__ __half g_A1[MTOK * D_];      // X lo split
__device__ __half g_B0[NTOT * D_];      // W hi split, PERMUTED row order
__device__ __half g_B1[NTOT * D_];      // W lo split, PERMUTED row order

// Column permutation: every 48-block = [32 w13-cols][16 w2-cols] so each warp
// tile gets a uniform 2:1 blend of 2-pass and 3-pass columns.
// Original concat: w1=[0,512) w2=[512,1024) w3=[1024,1536).
__device__ __forceinline__ int perm_to_orig(int p) {
    const int b = p / 48, r = p % 48;
    if (r < 32) { const int u = b * 32 + r; return (u < 512) ? u : u + 512; }
    return 512 + b * 16 + (r - 32);
}

// ---------------------------------------------------------------------------
// Kernel 0: split fp32 -> fp16 hi/lo. B written in permuted row order.
// ---------------------------------------------------------------------------
#define XFL   (MTOK * D_)              // 524288 floats in X
#define TOTG  ((MTOK + NTOT) * D_ / 8) // 163840 groups of 8

__global__ __launch_bounds__(256) void split_kernel(
    const float* __restrict__ X,
    const float* __restrict__ Win,
    const float* __restrict__ Wout,
    const float* __restrict__ Wb)
{
    const int g = blockIdx.x * 256 + threadIdx.x;
    if (g >= TOTG) return;
    const int q = g * 8;

    const float* src;
    __half *d0, *d1;
    if (q < XFL) {
        src = X + q;
        d0 = g_A0 + q;  d1 = g_A1 + q;
    } else {
        const int wq = q - XFL;
        const int np = wq >> 9;            // permuted row
        const int k  = wq & (D_ - 1);
        const int o  = perm_to_orig(np);   // original concat col
        src = (o < D_ ? Win + o * D_
                      : (o < 2 * D_ ? Wout + (o - D_) * D_
                                    : Wb + (o - 2 * D_) * D_)) + k;
        d0 = g_B0 + wq;  d1 = g_B1 + wq;
    }
    const float4 v0 = reinterpret_cast<const float4*>(src)[0];
    const float4 v1 = reinterpret_cast<const float4*>(src)[1];
    float f[8] = {v0.x, v0.y, v0.z, v0.w, v1.x, v1.y, v1.z, v1.w};
    __half hi[8], lo[8];
    #pragma unroll
    for (int i = 0; i < 8; ++i) {
        hi[i] = __float2half_rn(f[i]);
        lo[i] = __float2half_rn(f[i] - __half2float(hi[i]));
    }
    uint4 sh, sl;
    sh.x = *(uint32_t*)&hi[0]; sh.y = *(uint32_t*)&hi[2];
    sh.z = *(uint32_t*)&hi[4]; sh.w = *(uint32_t*)&hi[6];
    sl.x = *(uint32_t*)&lo[0]; sl.y = *(uint32_t*)&lo[2];
    sl.z = *(uint32_t*)&lo[4]; sl.w = *(uint32_t*)&lo[6];
    *reinterpret_cast<uint4*>(d0) = sh;
    *reinterpret_cast<uint4*>(d1) = sl;
}

// ---------------------------------------------------------------------------
// Kernel 1: GEMM, mixed pass-count. BM=128 BN=96 BK=32, grid 8x16 = 128 CTAs.
// Warp tile 32x48: atoms j=0..3 -> w13 cols (2-pass: ah*(bh+bl));
//                  atoms j=4..5 -> w2 cols  (3-pass: full split, exact).
// ---------------------------------------------------------------------------
#define BM 128
#define BN 96
#define BK 32
#define KP 40
#define A_OFF   0
#define A1_OFF  (BM * KP)
#define B_OFF   (2 * BM * KP)
#define B1_OFF  (2 * BM * KP + BN * KP)
#define STAGE_H (2 * BM * KP + 2 * BN * KP)  // 17920 halves
#define GSMEM   (2 * STAGE_H * 2)            // 71680 B

__device__ __forceinline__ void cp16(uint32_t smem, const void* gmem) {
    asm volatile("cp.async.cg.shared.global [%0], [%1], 16;\n"
                 :: "r"(smem), "l"(gmem));
}

__device__ __forceinline__ void mma_f16(float* c,
    uint32_t a0, uint32_t a1, uint32_t a2, uint32_t a3,
    uint32_t b0, uint32_t b1)
{
    asm volatile(
        "mma.sync.aligned.m16n8k16.row.col.f32.f16.f16.f32 "
        "{%0,%1,%2,%3}, {%4,%5,%6,%7}, {%8,%9}, {%0,%1,%2,%3};"
        : "+f"(c[0]), "+f"(c[1]), "+f"(c[2]), "+f"(c[3])
        : "r"(a0), "r"(a1), "r"(a2), "r"(a3), "r"(b0), "r"(b1));
}

__global__ __launch_bounds__(256, 1) void gemm3_f16()
{
    extern __shared__ __half sm[];

    const int tid   = threadIdx.x;
    const int lane  = tid & 31;
    const int wid   = tid >> 5;
    const int warpM = wid >> 1;         // 0..3
    const int warpN = wid & 1;          // 0..1
    const int gID   = lane >> 2;        // 0..7
    const int tIG   = lane & 3;         // 0..3
    const int m0    = blockIdx.x * BM;
    const int n0    = blockIdx.y * BN;  // permuted col base

    const uint32_t sbase = (uint32_t)__cvta_generic_to_shared(sm);

    float acc[2][6][4];
    #pragma unroll
    for (int i = 0; i < 2; i++)
        #pragma unroll
        for (int j = 0; j < 6; j++)
            #pragma unroll
            for (int q = 0; q < 4; q++) acc[i][j][q] = 0.f;

    auto issue = [&](int t, int stg) {
        const int k0 = t * BK;
        const uint32_t st = sbase + (uint32_t)(stg * STAGE_H) * 2u;
        #pragma unroll
        for (int it = 0; it < 2; ++it) {
            const int c = tid + it * 256;
            const int r = c >> 2, qd = c & 3;
            const uint32_t so = (uint32_t)(r * KP + qd * 8) * 2u;
            cp16(st + A_OFF * 2u + so,  g_A0 + (m0 + r) * D_ + k0 + qd * 8);
            cp16(st + A1_OFF * 2u + so, g_A1 + (m0 + r) * D_ + k0 + qd * 8);
        }
        #pragma unroll
        for (int c = tid; c < 384; c += 256) {
            const int r = c >> 2, qd = c & 3;
            const uint32_t so = (uint32_t)(r * KP + qd * 8) * 2u;
            cp16(st + B_OFF * 2u + so,  g_B0 + (n0 + r) * D_ + k0 + qd * 8);
            cp16(st + B1_OFF * 2u + so, g_B1 + (n0 + r) * D_ + k0 + qd * 8);
        }
        asm volatile("cp.async.commit_group;");
    };

    auto compute = [&](int stg) {
        const __half* Ah = sm + stg * STAGE_H + A_OFF;
        const __half* Al = sm + stg * STAGE_H + A1_OFF;
        const __half* Bh = sm + stg * STAGE_H + B_OFF;
        const __half* Bl = sm + stg * STAGE_H + B1_OFF;
        #pragma unroll
        for (int kk = 0; kk < BK; kk += 16) {
            uint32_t ah[2][4], al[2][4], bh[6][2], bl[6][2];
            #pragma unroll
            for (int i = 0; i < 2; ++i) {
                const int r = warpM * 32 + i * 16 + gID;
                const int c = kk + 2 * tIG;
                ah[i][0] = *(const uint32_t*)&Ah[r * KP + c];
                ah[i][1] = *(const uint32_t*)&Ah[(r + 8) * KP + c];
                ah[i][2] = *(const uint32_t*)&Ah[r * KP + c + 8];
                ah[i][3] = *(const uint32_t*)&Ah[(r + 8) * KP + c + 8];
                al[i][0] = *(const uint32_t*)&Al[r * KP + c];
                al[i][1] = *(const uint32_t*)&Al[(r + 8) * KP + c];
                al[i][2] = *(const uint32_t*)&Al[r * KP + c + 8];
                al[i][3] = *(const uint32_t*)&Al[(r + 8) * KP + c + 8];
            }
            #pragma unroll
            for (int j = 0; j < 6; ++j) {
                const int n = warpN * 48 + j * 8 + gID;
                const int c = kk + 2 * tIG;
                bh[j][0] = *(const uint32_t*)&Bh[n * KP + c];
                bh[j][1] = *(const uint32_t*)&Bh[n * KP + c + 8];
                bl[j][0] = *(const uint32_t*)&Bl[n * KP + c];
                bl[j][1] = *(const uint32_t*)&Bl[n * KP + c + 8];
            }
            // Pass 1: ah*bl for ALL atoms (w13: captures B-lo; w2: hi*lo term)
            #pragma unroll
            for (int i = 0; i < 2; ++i)
                #pragma unroll
                for (int j = 0; j < 6; ++j)
                    mma_f16(acc[i][j], ah[i][0], ah[i][1], ah[i][2], ah[i][3],
                            bl[j][0], bl[j][1]);
            // Pass 2: al*bh only for w2 atoms (j=4,5)
            #pragma unroll
            for (int i = 0; i < 2; ++i)
                #pragma unroll
                for (int j = 4; j < 6; ++j)
                    mma_f16(acc[i][j], al[i][0], al[i][1], al[i][2], al[i][3],
                            bh[j][0], bh[j][1]);
            // Pass 3: ah*bh for ALL atoms
            #pragma unroll
            for (int i = 0; i < 2; ++i)
                #pragma unroll
                for (int j = 0; j < 6; ++j)
                    mma_f16(acc[i][j], ah[i][0], ah[i][1], ah[i][2], ah[i][3],
                            bh[j][0], bh[j][1]);
        }
    };

    constexpr int T = D_ / BK;   // 16
    issue(0, 0);
    #pragma unroll 1
    for (int t = 0; t < T; ++t) {
        if (t + 1 < T) {
            issue(t + 1, (t + 1) & 1);
            asm volatile("cp.async.wait_group 1;");
        } else {
            asm volatile("cp.async.wait_group 0;");
        }
        __syncthreads();
        compute(t & 1);
        __syncthreads();
    }

    // Epilogue: un-permute columns, store float2 into ORIGINAL-layout g_P.
    // Consecutive permuted cols (2*tIG, 2*tIG+1) stay in one region -> the
    // original cols are also consecutive, so float2 stores remain valid.
    #pragma unroll
    for (int i = 0; i < 2; ++i) {
        const int r = m0 + warpM * 32 + i * 16 + gID;
        #pragma unroll
        for (int j = 0; j < 6; ++j) {
            const int cp = n0 + warpN * 48 + j * 8 + 2 * tIG;
            const int co = perm_to_orig(cp);
            *reinterpret_cast<float2*>(&g_P[r * NTOT + co]) =
                make_float2(acc[i][j][0], acc[i][j][1]);
            *reinterpret_cast<float2*>(&g_P[(r + 8) * NTOT + co]) =
                make_float2(acc[i][j][2], acc[i][j][3]);
        }
    }
}

// ---------------------------------------------------------------------------
// Kernel 2: finalize, warp-per-token. No smem, no __syncthreads.
// 256 blocks x 128 thr; each warp owns one token; 16 LDG.128 in flight/thread.
// ---------------------------------------------------------------------------
__global__ __launch_bounds__(128) void finalize_kernel(
    const float* __restrict__ X, float* __restrict__ Y)
{
    const int warp = threadIdx.x >> 5;
    const int lane = threadIdx.x & 31;
    const int m    = blockIdx.x * 4 + warp;
    const float* x = X + m * D_;
    const float* p = g_P + m * NTOT;   // w1 | w2 | w3

    float4 a[4], xx[4], c[4], v[4];
    #pragma unroll
    for (int q = 0; q < 4; ++q) {
        const int off = q * 128 + lane * 4;
        a[q]  = *reinterpret_cast<const float4*>(&p[off]);
        xx[q] = *reinterpret_cast<const float4*>(&x[off]);
        v[q]  = *reinterpret_cast<const float4*>(&p[D_ + off]);
        c[q]  = *reinterpret_cast<const float4*>(&p[2 * D_ + off]);
    }

    float sw1 = 0.f, sw1q = 0.f, sx = 0.f, sw1x = 0.f, sw3 = 0.f, sw3q = 0.f;
    #pragma unroll
    for (int q = 0; q < 4; ++q) {
        sw1  += (a[q].x + a[q].y) + (a[q].z + a[q].w);
        sw1q += (a[q].x * a[q].x + a[q].y * a[q].y)
              + (a[q].z * a[q].z + a[q].w * a[q].w);
        sx   += (xx[q].x + xx[q].y) + (xx[q].z + xx[q].w);
        sw1x += (a[q].x * xx[q].x + a[q].y * xx[q].y)
              + (a[q].z * xx[q].z + a[q].w * xx[q].w);
        sw3  += (c[q].x + c[q].y) + (c[q].z + c[q].w);
        sw3q += (c[q].x * c[q].x + c[q].y * c[q].y)
              + (c[q].z * c[q].z + c[q].w * c[q].w);
    }
    #pragma unroll
    for (int o = 16; o; o >>= 1) {
        sw1  += __shfl_xor_sync(0xffffffffu, sw1,  o);
        sw1q += __shfl_xor_sync(0xffffffffu, sw1q, o);
        sx   += __shfl_xor_sync(0xffffffffu, sx,   o);
        sw1x += __shfl_xor_sync(0xffffffffu, sw1x, o);
        sw3  += __shfl_xor_sync(0xffffffffu, sw3,  o);
        sw3q += __shfl_xor_sync(0xffffffffu, sw3q, o);
    }

    const float invD = 1.0f / (float)D_;
    const float mu1  = sw1 * invD;
    const float var1 = fmaxf(sw1q * invD - mu1 * mu1, 0.f);
    const float s    = sw1x - mu1 * sx;
    const float mu3  = sw3 * invD;
    const float var3 = fmaxf(sw3q * invD - mu3 * mu3, 0.f);
    const float inv3 = rsqrtf(var3 + EPS_);

    #pragma unroll
    for (int q = 0; q < 4; ++q) {
        float4 out;
        out.x = v[q].x * s * rsqrtf(v[q].x * v[q].x * var1 + EPS_)
              + (c[q].x - mu3) * inv3;
        out.y = v[q].y * s * rsqrtf(v[q].y * v[q].y * var1 + EPS_)
              + (c[q].y - mu3) * inv3;
        out.z = v[q].z * s * rsqrtf(v[q].z * v[q].z * var1 + EPS_)
              + (c[q].z - mu3) * inv3;
        out.w = v[q].w * s * rsqrtf(v[q].w * v[q].w * var1 + EPS_)
              + (c[q].w - mu3) * inv3;
        *reinterpret_cast<float4*>(&Y[m * D_ + q * 128 + lane * 4]) = out;
    }
}

// ---------------------------------------------------------------------------
extern "C" void kernel_launch(void* const* d_in, const int* in_sizes, int n_in,
                              void* d_out, int out_size)
{
    const float* X    = (const float*)d_in[0];
    const float* Win  = (const float*)d_in[1];
    const float* Wout = (const float*)d_in[2];
    const float* Wb   = (const float*)d_in[3];
    float* Y = (float*)d_out;

    cudaFuncSetAttribute(gemm3_f16,
                         cudaFuncAttributeMaxDynamicSharedMemorySize, GSMEM);

    split_kernel<<<(TOTG + 255) / 256, 256>>>(X, Win, Wout, Wb);
    gemm3_f16<<<dim3(MTOK / BM, NTOT / BN), 256, GSMEM>>>();
    finalize_kernel<<<MTOK / 4, 128>>>(X, Y);
}

// round 10
// speedup vs baseline: 1.2368x; 1.0769x over previous
#include <cuda_runtime.h>
#include <cuda_fp16.h>
#include <cstdint>

// Problem constants
#define B_    2
#define S_    512
#define D_    512
#define MTOK  1024          // B*S tokens
#define NTOT  1536          // w1 | w2 | w3
#define EPS_  1e-5f

// Static device scratch
__device__ float  g_P[MTOK * NTOT];     // 6 MB projections (ORIGINAL col order)
__device__ __half g_A0[MTOK * D_];      // X hi split
__device__ __half g_A1[MTOK * D_];      // X lo split
__device__ __half g_B0[NTOT * D_];      // W hi split, PERMUTED row order
__device__ __half g_B1[512 * D_];       // W lo split, w2 rows ONLY (compact)

// Column permutation: every 48-block = [32 w13-cols][16 w2-cols].
// Original concat: w1=[0,512) w2=[512,1024) w3=[1024,1536).
__device__ __forceinline__ int perm_to_orig(int p) {
    const int b = p / 48, r = p % 48;
    if (r < 32) { const int u = b * 32 + r; return (u < 512) ? u : u + 512; }
    return 512 + b * 16 + (r - 32);
}

// ---------------------------------------------------------------------------
// Kernel 0: split fp32 -> fp16 hi/lo. B-hi full permuted; B-lo only w2 rows.
// ---------------------------------------------------------------------------
#define XFL   (MTOK * D_)              // 524288 floats in X
#define TOTG  ((MTOK + NTOT) * D_ / 8) // 163840 groups of 8

__global__ __launch_bounds__(256) void split_kernel(
    const float* __restrict__ X,
    const float* __restrict__ Win,
    const float* __restrict__ Wout,
    const float* __restrict__ Wb)
{
    const int g = blockIdx.x * 256 + threadIdx.x;
    if (g >= TOTG) return;
    const int q = g * 8;

    const float* src;
    __half *d0, *d1 = nullptr;
    if (q < XFL) {
        src = X + q;
        d0 = g_A0 + q;  d1 = g_A1 + q;
    } else {
        const int wq = q - XFL;
        const int np = wq >> 9;            // permuted row
        const int k  = wq & (D_ - 1);
        const int o  = perm_to_orig(np);   // original concat col
        src = (o < D_ ? Win + o * D_
                      : (o < 2 * D_ ? Wout + (o - D_) * D_
                                    : Wb + (o - 2 * D_) * D_)) + k;
        d0 = g_B0 + wq;
        const int r48 = np % 48;
        if (r48 >= 32)                     // w2 row -> compact lo array
            d1 = g_B1 + ((np / 48) * 16 + (r48 - 32)) * D_ + k;
    }
    const float4 v0 = reinterpret_cast<const float4*>(src)[0];
    const float4 v1 = reinterpret_cast<const float4*>(src)[1];
    float f[8] = {v0.x, v0.y, v0.z, v0.w, v1.x, v1.y, v1.z, v1.w};
    __half hi[8], lo[8];
    #pragma unroll
    for (int i = 0; i < 8; ++i) {
        hi[i] = __float2half_rn(f[i]);
        lo[i] = __float2half_rn(f[i] - __half2float(hi[i]));
    }
    uint4 sh, sl;
    sh.x = *(uint32_t*)&hi[0]; sh.y = *(uint32_t*)&hi[2];
    sh.z = *(uint32_t*)&hi[4]; sh.w = *(uint32_t*)&hi[6];
    sl.x = *(uint32_t*)&lo[0]; sl.y = *(uint32_t*)&lo[2];
    sl.z = *(uint32_t*)&lo[4]; sl.w = *(uint32_t*)&lo[6];
    *reinterpret_cast<uint4*>(d0) = sh;
    if (d1) *reinterpret_cast<uint4*>(d1) = sl;
}

// ---------------------------------------------------------------------------
// Kernel 1: GEMM, mixed pass-count. BM=128 BN=96 BK=32, grid 8x16 = 128 CTAs.
// Warp tile 32x48: atoms j=0..3 -> w13 cols (1-pass: ah*bh);
//                  atoms j=4..5 -> w2 cols  (3-pass: exact split).
// Per chunk per warp: 20 MMAs (was 28).
// ---------------------------------------------------------------------------
#define BM 128
#define BN 96
#define BK 32
#define KP 40
#define A_OFF   0
#define A1_OFF  (BM * KP)                    // 5120
#define B_OFF   (2 * BM * KP)                // 10240
#define B1_OFF  (2 * BM * KP + BN * KP)      // 14080 (compact: 32 rows)
#define STAGE_H (2 * BM * KP + BN * KP + 32 * KP)  // 15360 halves
#define GSMEM   (2 * STAGE_H * 2)                  // 61440 B

__device__ __forceinline__ void cp16(uint32_t smem, const void* gmem) {
    asm volatile("cp.async.cg.shared.global [%0], [%1], 16;\n"
                 :: "r"(smem), "l"(gmem));
}

__device__ __forceinline__ void mma_f16(float* c,
    uint32_t a0, uint32_t a1, uint32_t a2, uint32_t a3,
    uint32_t b0, uint32_t b1)
{
    asm volatile(
        "mma.sync.aligned.m16n8k16.row.col.f32.f16.f16.f32 "
        "{%0,%1,%2,%3}, {%4,%5,%6,%7}, {%8,%9}, {%0,%1,%2,%3};"
        : "+f"(c[0]), "+f"(c[1]), "+f"(c[2]), "+f"(c[3])
        : "r"(a0), "r"(a1), "r"(a2), "r"(a3), "r"(b0), "r"(b1));
}

__global__ __launch_bounds__(256, 1) void gemm3_f16()
{
    extern __shared__ __half sm[];

    const int tid   = threadIdx.x;
    const int lane  = tid & 31;
    const int wid   = tid >> 5;
    const int warpM = wid >> 1;         // 0..3
    const int warpN = wid & 1;          // 0..1
    const int gID   = lane >> 2;        // 0..7
    const int tIG   = lane & 3;         // 0..3
    const int m0    = blockIdx.x * BM;
    const int n0    = blockIdx.y * BN;  // permuted col base
    const int w2b   = blockIdx.y * 32;  // compact B1 row base for this CTA

    const uint32_t sbase = (uint32_t)__cvta_generic_to_shared(sm);

    float acc[2][6][4];
    #pragma unroll
    for (int i = 0; i < 2; i++)
        #pragma unroll
        for (int j = 0; j < 6; j++)
            #pragma unroll
            for (int q = 0; q < 4; q++) acc[i][j][q] = 0.f;

    auto issue = [&](int t, int stg) {
        const int k0 = t * BK;
        const uint32_t st = sbase + (uint32_t)(stg * STAGE_H) * 2u;
        #pragma unroll
        for (int it = 0; it < 2; ++it) {
            const int c = tid + it * 256;
            const int r = c >> 2, qd = c & 3;
            const uint32_t so = (uint32_t)(r * KP + qd * 8) * 2u;
            cp16(st + A_OFF * 2u + so,  g_A0 + (m0 + r) * D_ + k0 + qd * 8);
            cp16(st + A1_OFF * 2u + so, g_A1 + (m0 + r) * D_ + k0 + qd * 8);
        }
        #pragma unroll
        for (int c = tid; c < 384; c += 256) {
            const int r = c >> 2, qd = c & 3;
            cp16(st + B_OFF * 2u + (uint32_t)(r * KP + qd * 8) * 2u,
                 g_B0 + (n0 + r) * D_ + k0 + qd * 8);
        }
        if (tid < 128) {                 // B1 compact: 32 rows x 4 chunks
            const int r = tid >> 2, qd = tid & 3;
            cp16(st + B1_OFF * 2u + (uint32_t)(r * KP + qd * 8) * 2u,
                 g_B1 + (w2b + r) * D_ + k0 + qd * 8);
        }
        asm volatile("cp.async.commit_group;");
    };

    auto compute = [&](int stg) {
        const __half* Ah = sm + stg * STAGE_H + A_OFF;
        const __half* Al = sm + stg * STAGE_H + A1_OFF;
        const __half* Bh = sm + stg * STAGE_H + B_OFF;
        const __half* Bl = sm + stg * STAGE_H + B1_OFF;
        #pragma unroll
        for (int kk = 0; kk < BK; kk += 16) {
            uint32_t ah[2][4], al[2][4], bh[6][2], bl[2][2];
            #pragma unroll
            for (int i = 0; i < 2; ++i) {
                const int r = warpM * 32 + i * 16 + gID;
                const int c = kk + 2 * tIG;
                ah[i][0] = *(const uint32_t*)&Ah[r * KP + c];
                ah[i][1] = *(const uint32_t*)&Ah[(r + 8) * KP + c];
                ah[i][2] = *(const uint32_t*)&Ah[r * KP + c + 8];
                ah[i][3] = *(const uint32_t*)&Ah[(r + 8) * KP + c + 8];
                al[i][0] = *(const uint32_t*)&Al[r * KP + c];
                al[i][1] = *(const uint32_t*)&Al[(r + 8) * KP + c];
                al[i][2] = *(const uint32_t*)&Al[r * KP + c + 8];
                al[i][3] = *(const uint32_t*)&Al[(r + 8) * KP + c + 8];
            }
            #pragma unroll
            for (int j = 0; j < 6; ++j) {
                const int n = warpN * 48 + j * 8 + gID;
                const int c = kk + 2 * tIG;
                bh[j][0] = *(const uint32_t*)&Bh[n * KP + c];
                bh[j][1] = *(const uint32_t*)&Bh[n * KP + c + 8];
            }
            #pragma unroll
            for (int jj = 0; jj < 2; ++jj) {   // compact lo rows, w2 atoms only
                const int n = warpN * 16 + jj * 8 + gID;
                const int c = kk + 2 * tIG;
                bl[jj][0] = *(const uint32_t*)&Bl[n * KP + c];
                bl[jj][1] = *(const uint32_t*)&Bl[n * KP + c + 8];
            }
            // Pass 1 (w2 only): ah*bl
            #pragma unroll
            for (int i = 0; i < 2; ++i)
                #pragma unroll
                for (int jj = 0; jj < 2; ++jj)
                    mma_f16(acc[i][4 + jj], ah[i][0], ah[i][1], ah[i][2], ah[i][3],
                            bl[jj][0], bl[jj][1]);
            // Pass 2 (w2 only): al*bh
            #pragma unroll
            for (int i = 0; i < 2; ++i)
                #pragma unroll
                for (int jj = 0; jj < 2; ++jj)
                    mma_f16(acc[i][4 + jj], al[i][0], al[i][1], al[i][2], al[i][3],
                            bh[4 + jj][0], bh[4 + jj][1]);
            // Pass 3 (all atoms): ah*bh
            #pragma unroll
            for (int i = 0; i < 2; ++i)
                #pragma unroll
                for (int j = 0; j < 6; ++j)
                    mma_f16(acc[i][j], ah[i][0], ah[i][1], ah[i][2], ah[i][3],
                            bh[j][0], bh[j][1]);
        }
    };

    constexpr int T = D_ / BK;   // 16
    issue(0, 0);
    #pragma unroll 1
    for (int t = 0; t < T; ++t) {
        if (t + 1 < T) {
            issue(t + 1, (t + 1) & 1);
            asm volatile("cp.async.wait_group 1;");
        } else {
            asm volatile("cp.async.wait_group 0;");
        }
        __syncthreads();
        compute(t & 1);
        __syncthreads();
    }

    // Epilogue: un-permute columns, store float2 into ORIGINAL-layout g_P.
    #pragma unroll
    for (int i = 0; i < 2; ++i) {
        const int r = m0 + warpM * 32 + i * 16 + gID;
        #pragma unroll
        for (int j = 0; j < 6; ++j) {
            const int cp = n0 + warpN * 48 + j * 8 + 2 * tIG;
            const int co = perm_to_orig(cp);
            *reinterpret_cast<float2*>(&g_P[r * NTOT + co]) =
                make_float2(acc[i][j][0], acc[i][j][1]);
            *reinterpret_cast<float2*>(&g_P[(r + 8) * NTOT + co]) =
                make_float2(acc[i][j][2], acc[i][j][3]);
        }
    }
}

// ---------------------------------------------------------------------------
// Kernel 2: finalize, warp-per-token. No smem, no __syncthreads.
// ---------------------------------------------------------------------------
__global__ __launch_bounds__(128) void finalize_kernel(
    const float* __restrict__ X, float* __restrict__ Y)
{
    const int warp = threadIdx.x >> 5;
    const int lane = threadIdx.x & 31;
    const int m    = blockIdx.x * 4 + warp;
    const float* x = X + m * D_;
    const float* p = g_P + m * NTOT;   // w1 | w2 | w3

    float4 a[4], xx[4], c[4], v[4];
    #pragma unroll
    for (int q = 0; q < 4; ++q) {
        const int off = q * 128 + lane * 4;
        a[q]  = *reinterpret_cast<const float4*>(&p[off]);
        xx[q] = *reinterpret_cast<const float4*>(&x[off]);
        v[q]  = *reinterpret_cast<const float4*>(&p[D_ + off]);
        c[q]  = *reinterpret_cast<const float4*>(&p[2 * D_ + off]);
    }

    float sw1 = 0.f, sw1q = 0.f, sx = 0.f, sw1x = 0.f, sw3 = 0.f, sw3q = 0.f;
    #pragma unroll
    for (int q = 0; q < 4; ++q) {
        sw1  += (a[q].x + a[q].y) + (a[q].z + a[q].w);
        sw1q += (a[q].x * a[q].x + a[q].y * a[q].y)
              + (a[q].z * a[q].z + a[q].w * a[q].w);
        sx   += (xx[q].x + xx[q].y) + (xx[q].z + xx[q].w);
        sw1x += (a[q].x * xx[q].x + a[q].y * xx[q].y)
              + (a[q].z * xx[q].z + a[q].w * xx[q].w);
        sw3  += (c[q].x + c[q].y) + (c[q].z + c[q].w);
        sw3q += (c[q].x * c[q].x + c[q].y * c[q].y)
              + (c[q].z * c[q].z + c[q].w * c[q].w);
    }
    #pragma unroll
    for (int o = 16; o; o >>= 1) {
        sw1  += __shfl_xor_sync(0xffffffffu, sw1,  o);
        sw1q += __shfl_xor_sync(0xffffffffu, sw1q, o);
        sx   += __shfl_xor_sync(0xffffffffu, sx,   o);
        sw1x += __shfl_xor_sync(0xffffffffu, sw1x, o);
        sw3  += __shfl_xor_sync(0xffffffffu, sw3,  o);
        sw3q += __shfl_xor_sync(0xffffffffu, sw3q, o);
    }

    const float invD = 1.0f / (float)D_;
    const float mu1  = sw1 * invD;
    const float var1 = fmaxf(sw1q * invD - mu1 * mu1, 0.f);
    const float s    = sw1x - mu1 * sx;
    const float mu3  = sw3 * invD;
    const float var3 = fmaxf(sw3q * invD - mu3 * mu3, 0.f);
    const float inv3 = rsqrtf(var3 + EPS_);

    #pragma unroll
    for (int q = 0; q < 4; ++q) {
        float4 out;
        out.x = v[q].x * s * rsqrtf(v[q].x * v[q].x * var1 + EPS_)
              + (c[q].x - mu3) * inv3;
        out.y = v[q].y * s * rsqrtf(v[q].y * v[q].y * var1 + EPS_)
              + (c[q].y - mu3) * inv3;
        out.z = v[q].z * s * rsqrtf(v[q].z * v[q].z * var1 + EPS_)
              + (c[q].z - mu3) * inv3;
        out.w = v[q].w * s * rsqrtf(v[q].w * v[q].w * var1 + EPS_)
              + (c[q].w - mu3) * inv3;
        *reinterpret_cast<float4*>(&Y[m * D_ + q * 128 + lane * 4]) = out;
    }
}

// ---------------------------------------------------------------------------
extern "C" void kernel_launch(void* const* d_in, const int* in_sizes, int n_in,
                              void* d_out, int out_size)
{
    const float* X    = (const float*)d_in[0];
    const float* Win  = (const float*)d_in[1];
    const float* Wout = (const float*)d_in[2];
    const float* Wb   = (const float*)d_in[3];
    float* Y = (float*)d_out;

    cudaFuncSetAttribute(gemm3_f16,
                         cudaFuncAttributeMaxDynamicSharedMemorySize, GSMEM);

    split_kernel<<<(TOTG + 255) / 256, 256>>>(X, Win, Wout, Wb);
    gemm3_f16<<<dim3(MTOK / BM, NTOT / BN), 256, GSMEM>>>();
    finalize_kernel<<<MTOK / 4, 128>>>(X, Y);
}

// round 11
// speedup vs baseline: 1.2383x; 1.0012x over previous
#include <cuda_runtime.h>
#include <cuda_fp16.h>
#include <cstdint>

// Problem constants
#define B_    2
#define S_    512
#define D_    512
#define MTOK  1024          // B*S tokens
#define NTOT  1536          // w1 | w2 | w3
#define EPS_  1e-5f

// Static device scratch
__device__ float  g_P[MTOK * NTOT];     // w2|w3 projections (w1 region unused)
__device__ float4 g_W1R[MTOK][16];      // per-token partials: sum,sq,dot,sx
__device__ __half g_A0[MTOK * D_];      // X hi split
__device__ __half g_A1[MTOK * D_];      // X lo split
__device__ __half g_B0[NTOT * D_];      // W hi split, PERMUTED row order
__device__ __half g_B1[512 * D_];       // W lo split, w2 rows ONLY (compact)

// Column permutation: every 48-block = [32 w13-cols][16 w2-cols].
// Original concat: w1=[0,512) w2=[512,1024) w3=[1024,1536).
__device__ __forceinline__ int perm_to_orig(int p) {
    const int b = p / 48, r = p % 48;
    if (r < 32) { const int u = b * 32 + r; return (u < 512) ? u : u + 512; }
    return 512 + b * 16 + (r - 32);
}

// ---------------------------------------------------------------------------
// Kernel 0: split fp32 -> fp16 hi/lo. B-hi full permuted; B-lo only w2 rows.
// ---------------------------------------------------------------------------
#define XFL   (MTOK * D_)              // 524288 floats in X
#define TOTG  ((MTOK + NTOT) * D_ / 8) // 163840 groups of 8

__global__ __launch_bounds__(256) void split_kernel(
    const float* __restrict__ X,
    const float* __restrict__ Win,
    const float* __restrict__ Wout,
    const float* __restrict__ Wb)
{
    const int g = blockIdx.x * 256 + threadIdx.x;
    if (g >= TOTG) return;
    const int q = g * 8;

    const float* src;
    __half *d0, *d1 = nullptr;
    if (q < XFL) {
        src = X + q;
        d0 = g_A0 + q;  d1 = g_A1 + q;
    } else {
        const int wq = q - XFL;
        const int np = wq >> 9;            // permuted row
        const int k  = wq & (D_ - 1);
        const int o  = perm_to_orig(np);   // original concat col
        src = (o < D_ ? Win + o * D_
                      : (o < 2 * D_ ? Wout + (o - D_) * D_
                                    : Wb + (o - 2 * D_) * D_)) + k;
        d0 = g_B0 + wq;
        const int r48 = np % 48;
        if (r48 >= 32)                     // w2 row -> compact lo array
            d1 = g_B1 + ((np / 48) * 16 + (r48 - 32)) * D_ + k;
    }
    const float4 v0 = reinterpret_cast<const float4*>(src)[0];
    const float4 v1 = reinterpret_cast<const float4*>(src)[1];
    float f[8] = {v0.x, v0.y, v0.z, v0.w, v1.x, v1.y, v1.z, v1.w};
    __half hi[8], lo[8];
    #pragma unroll
    for (int i = 0; i < 8; ++i) {
        hi[i] = __float2half_rn(f[i]);
        lo[i] = __float2half_rn(f[i] - __half2float(hi[i]));
    }
    uint4 sh, sl;
    sh.x = *(uint32_t*)&hi[0]; sh.y = *(uint32_t*)&hi[2];
    sh.z = *(uint32_t*)&hi[4]; sh.w = *(uint32_t*)&hi[6];
    sl.x = *(uint32_t*)&lo[0]; sl.y = *(uint32_t*)&lo[2];
    sl.z = *(uint32_t*)&lo[4]; sl.w = *(uint32_t*)&lo[6];
    *reinterpret_cast<uint4*>(d0) = sh;
    if (d1) *reinterpret_cast<uint4*>(d1) = sl;
}

// ---------------------------------------------------------------------------
// Kernel 1: GEMM, mixed pass-count, 3-stage pipeline, fused w1 reduction.
// BM=128 BN=96 BK=32, grid 8x16 = 128 CTAs.
// by<8: w13 atoms are w1 cols -> in-register reduction, no g_P store.
// by>=8: w13 atoms are w3 cols -> store. w2 atoms (all CTAs) -> store.
// ---------------------------------------------------------------------------
#define BM 128
#define BN 96
#define BK 32
#define KP 40
#define A_OFF   0
#define A1_OFF  (BM * KP)                    // 5120
#define B_OFF   (2 * BM * KP)                // 10240
#define B1_OFF  (2 * BM * KP + BN * KP)      // 14080 (compact: 32 rows)
#define STAGE_H (2 * BM * KP + BN * KP + 32 * KP)  // 15360 halves
#define NSTG    3
#define GSMEM   (NSTG * STAGE_H * 2)               // 92160 B

__device__ __forceinline__ void cp16(uint32_t smem, const void* gmem) {
    asm volatile("cp.async.cg.shared.global [%0], [%1], 16;\n"
                 :: "r"(smem), "l"(gmem));
}

__device__ __forceinline__ void mma_f16(float* c,
    uint32_t a0, uint32_t a1, uint32_t a2, uint32_t a3,
    uint32_t b0, uint32_t b1)
{
    asm volatile(
        "mma.sync.aligned.m16n8k16.row.col.f32.f16.f16.f32 "
        "{%0,%1,%2,%3}, {%4,%5,%6,%7}, {%8,%9}, {%0,%1,%2,%3};"
        : "+f"(c[0]), "+f"(c[1]), "+f"(c[2]), "+f"(c[3])
        : "r"(a0), "r"(a1), "r"(a2), "r"(a3), "r"(b0), "r"(b1));
}

__global__ __launch_bounds__(256, 1) void gemm3_f16(const float* __restrict__ X)
{
    extern __shared__ __half sm[];

    const int tid   = threadIdx.x;
    const int lane  = tid & 31;
    const int wid   = tid >> 5;
    const int warpM = wid >> 1;         // 0..3
    const int warpN = wid & 1;          // 0..1
    const int gID   = lane >> 2;        // 0..7
    const int tIG   = lane & 3;         // 0..3
    const int m0    = blockIdx.x * BM;
    const int by    = blockIdx.y;
    const int n0    = by * BN;          // permuted col base
    const int w2b   = by * 32;          // compact B1 row base

    const uint32_t sbase = (uint32_t)__cvta_generic_to_shared(sm);

    float acc[2][6][4];
    #pragma unroll
    for (int i = 0; i < 2; i++)
        #pragma unroll
        for (int j = 0; j < 6; j++)
            #pragma unroll
            for (int q = 0; q < 4; q++) acc[i][j][q] = 0.f;

    auto issue = [&](int t, int stg) {
        const int k0 = t * BK;
        const uint32_t st = sbase + (uint32_t)(stg * STAGE_H) * 2u;
        #pragma unroll
        for (int it = 0; it < 2; ++it) {
            const int c = tid + it * 256;
            const int r = c >> 2, qd = c & 3;
            const uint32_t so = (uint32_t)(r * KP + qd * 8) * 2u;
            cp16(st + A_OFF * 2u + so,  g_A0 + (m0 + r) * D_ + k0 + qd * 8);
            cp16(st + A1_OFF * 2u + so, g_A1 + (m0 + r) * D_ + k0 + qd * 8);
        }
        #pragma unroll
        for (int c = tid; c < 384; c += 256) {
            const int r = c >> 2, qd = c & 3;
            cp16(st + B_OFF * 2u + (uint32_t)(r * KP + qd * 8) * 2u,
                 g_B0 + (n0 + r) * D_ + k0 + qd * 8);
        }
        if (tid < 128) {                 // B1 compact: 32 rows x 4 chunks
            const int r = tid >> 2, qd = tid & 3;
            cp16(st + B1_OFF * 2u + (uint32_t)(r * KP + qd * 8) * 2u,
                 g_B1 + (w2b + r) * D_ + k0 + qd * 8);
        }
        asm volatile("cp.async.commit_group;");
    };

    auto compute = [&](int stg) {
        const __half* Ah = sm + stg * STAGE_H + A_OFF;
        const __half* Al = sm + stg * STAGE_H + A1_OFF;
        const __half* Bh = sm + stg * STAGE_H + B_OFF;
        const __half* Bl = sm + stg * STAGE_H + B1_OFF;
        #pragma unroll
        for (int kk = 0; kk < BK; kk += 16) {
            uint32_t ah[2][4], al[2][4], bh[6][2], bl[2][2];
            #pragma unroll
            for (int i = 0; i < 2; ++i) {
                const int r = warpM * 32 + i * 16 + gID;
                const int c = kk + 2 * tIG;
                ah[i][0] = *(const uint32_t*)&Ah[r * KP + c];
                ah[i][1] = *(const uint32_t*)&Ah[(r + 8) * KP + c];
                ah[i][2] = *(const uint32_t*)&Ah[r * KP + c + 8];
                ah[i][3] = *(const uint32_t*)&Ah[(r + 8) * KP + c + 8];
                al[i][0] = *(const uint32_t*)&Al[r * KP + c];
                al[i][1] = *(const uint32_t*)&Al[(r + 8) * KP + c];
                al[i][2] = *(const uint32_t*)&Al[r * KP + c + 8];
                al[i][3] = *(const uint32_t*)&Al[(r + 8) * KP + c + 8];
            }
            #pragma unroll
            for (int j = 0; j < 6; ++j) {
                const int n = warpN * 48 + j * 8 + gID;
                const int c = kk + 2 * tIG;
                bh[j][0] = *(const uint32_t*)&Bh[n * KP + c];
                bh[j][1] = *(const uint32_t*)&Bh[n * KP + c + 8];
            }
            #pragma unroll
            for (int jj = 0; jj < 2; ++jj) {
                const int n = warpN * 16 + jj * 8 + gID;
                const int c = kk + 2 * tIG;
                bl[jj][0] = *(const uint32_t*)&Bl[n * KP + c];
                bl[jj][1] = *(const uint32_t*)&Bl[n * KP + c + 8];
            }
            // w2 atoms: 3-pass exact
            #pragma unroll
            for (int i = 0; i < 2; ++i)
                #pragma unroll
                for (int jj = 0; jj < 2; ++jj)
                    mma_f16(acc[i][4 + jj], ah[i][0], ah[i][1], ah[i][2], ah[i][3],
                            bl[jj][0], bl[jj][1]);
            #pragma unroll
            for (int i = 0; i < 2; ++i)
                #pragma unroll
                for (int jj = 0; jj < 2; ++jj)
                    mma_f16(acc[i][4 + jj], al[i][0], al[i][1], al[i][2], al[i][3],
                            bh[4 + jj][0], bh[4 + jj][1]);
            // all atoms: ah*bh
            #pragma unroll
            for (int i = 0; i < 2; ++i)
                #pragma unroll
                for (int j = 0; j < 6; ++j)
                    mma_f16(acc[i][j], ah[i][0], ah[i][1], ah[i][2], ah[i][3],
                            bh[j][0], bh[j][1]);
        }
    };

    constexpr int T = D_ / BK;   // 16
    issue(0, 0);
    issue(1, 1);
    #pragma unroll 1
    for (int t = 0; t < T; ++t) {
        if (t + 1 < T) asm volatile("cp.async.wait_group 1;");
        else           asm volatile("cp.async.wait_group 0;");
        __syncthreads();
        compute(t % NSTG);
        __syncthreads();
        if (t + 2 < T) issue(t + 2, (t + 2) % NSTG);
    }

    // -------- Epilogue --------
    if (by < 8) {
        // w13 atoms are w1 columns: reduce in-register, write partials.
        const int ub = (2 * by + warpN) * 32;       // orig col base (32 cols)
        #pragma unroll
        for (int i = 0; i < 2; ++i)
            #pragma unroll
            for (int half = 0; half < 2; ++half) {
                const int row = m0 + warpM * 32 + i * 16 + half * 8 + gID;
                float s = 0.f, qd = 0.f, dx = 0.f, sx = 0.f;
                #pragma unroll
                for (int j = 0; j < 4; ++j) {
                    const float w1a = acc[i][j][half * 2 + 0];
                    const float w1b = acc[i][j][half * 2 + 1];
                    const float2 xv = *reinterpret_cast<const float2*>(
                        &X[row * D_ + ub + j * 8 + 2 * tIG]);
                    s  += w1a + w1b;
                    qd += w1a * w1a + w1b * w1b;
                    dx += w1a * xv.x + w1b * xv.y;
                    sx += xv.x + xv.y;
                }
                #pragma unroll
                for (int o = 1; o < 4; o <<= 1) {
                    s  += __shfl_xor_sync(0xffffffffu, s,  o);
                    qd += __shfl_xor_sync(0xffffffffu, qd, o);
                    dx += __shfl_xor_sync(0xffffffffu, dx, o);
                    sx += __shfl_xor_sync(0xffffffffu, sx, o);
                }
                if (tIG == 0)
                    g_W1R[row][by * 2 + warpN] = make_float4(s, qd, dx, sx);
            }
    } else {
        // w13 atoms are w3 columns: store to g_P.
        #pragma unroll
        for (int i = 0; i < 2; ++i) {
            const int r = m0 + warpM * 32 + i * 16 + gID;
            #pragma unroll
            for (int j = 0; j < 4; ++j) {
                const int cp = n0 + warpN * 48 + j * 8 + 2 * tIG;
                const int co = perm_to_orig(cp);
                *reinterpret_cast<float2*>(&g_P[r * NTOT + co]) =
                    make_float2(acc[i][j][0], acc[i][j][1]);
                *reinterpret_cast<float2*>(&g_P[(r + 8) * NTOT + co]) =
                    make_float2(acc[i][j][2], acc[i][j][3]);
            }
        }
    }
    // w2 atoms: store (all CTAs)
    #pragma unroll
    for (int i = 0; i < 2; ++i) {
        const int r = m0 + warpM * 32 + i * 16 + gID;
        #pragma unroll
        for (int j = 4; j < 6; ++j) {
            const int cp = n0 + warpN * 48 + j * 8 + 2 * tIG;
            const int co = perm_to_orig(cp);
            *reinterpret_cast<float2*>(&g_P[r * NTOT + co]) =
                make_float2(acc[i][j][0], acc[i][j][1]);
            *reinterpret_cast<float2*>(&g_P[(r + 8) * NTOT + co]) =
                make_float2(acc[i][j][2], acc[i][j][3]);
        }
    }
}

// ---------------------------------------------------------------------------
// Kernel 2: finalize, warp-per-token. Reads only w2, w3 + partials (no X, no w1).
// ---------------------------------------------------------------------------
__global__ __launch_bounds__(128) void finalize_kernel(float* __restrict__ Y)
{
    const int warp = threadIdx.x >> 5;
    const int lane = threadIdx.x & 31;
    const int m    = blockIdx.x * 4 + warp;
    const float* p = g_P + m * NTOT;

    // Gather the 16 w1 partials (lanes 0..15), reduce across warp.
    float4 pp = (lane < 16) ? g_W1R[m][lane] : make_float4(0.f, 0.f, 0.f, 0.f);
    #pragma unroll
    for (int o = 1; o < 32; o <<= 1) {
        pp.x += __shfl_xor_sync(0xffffffffu, pp.x, o);
        pp.y += __shfl_xor_sync(0xffffffffu, pp.y, o);
        pp.z += __shfl_xor_sync(0xffffffffu, pp.z, o);
        pp.w += __shfl_xor_sync(0xffffffffu, pp.w, o);
    }
    const float sw1 = pp.x, sw1q = pp.y, sw1x = pp.z, sx = pp.w;

    float4 v[4], c[4];
    #pragma unroll
    for (int q = 0; q < 4; ++q) {
        const int off = q * 128 + lane * 4;
        v[q] = *reinterpret_cast<const float4*>(&p[D_ + off]);       // w2
        c[q] = *reinterpret_cast<const float4*>(&p[2 * D_ + off]);   // w3
    }
    float sw3 = 0.f, sw3q = 0.f;
    #pragma unroll
    for (int q = 0; q < 4; ++q) {
        sw3  += (c[q].x + c[q].y) + (c[q].z + c[q].w);
        sw3q += (c[q].x * c[q].x + c[q].y * c[q].y)
              + (c[q].z * c[q].z + c[q].w * c[q].w);
    }
    #pragma unroll
    for (int o = 1; o < 32; o <<= 1) {
        sw3  += __shfl_xor_sync(0xffffffffu, sw3,  o);
        sw3q += __shfl_xor_sync(0xffffffffu, sw3q, o);
    }

    const float invD = 1.0f / (float)D_;
    const float mu1  = sw1 * invD;
    const float var1 = fmaxf(sw1q * invD - mu1 * mu1, 0.f);
    const float s    = sw1x - mu1 * sx;
    const float mu3  = sw3 * invD;
    const float var3 = fmaxf(sw3q * invD - mu3 * mu3, 0.f);
    const float inv3 = rsqrtf(var3 + EPS_);

    #pragma unroll
    for (int q = 0; q < 4; ++q) {
        float4 out;
        out.x = v[q].x * s * rsqrtf(v[q].x * v[q].x * var1 + EPS_)
              + (c[q].x - mu3) * inv3;
        out.y = v[q].y * s * rsqrtf(v[q].y * v[q].y * var1 + EPS_)
              + (c[q].y - mu3) * inv3;
        out.z = v[q].z * s * rsqrtf(v[q].z * v[q].z * var1 + EPS_)
              + (c[q].z - mu3) * inv3;
        out.w = v[q].w * s * rsqrtf(v[q].w * v[q].w * var1 + EPS_)
              + (c[q].w - mu3) * inv3;
        *reinterpret_cast<float4*>(&Y[m * D_ + q * 128 + lane * 4]) = out;
    }
}

// ---------------------------------------------------------------------------
extern "C" void kernel_launch(void* const* d_in, const int* in_sizes, int n_in,
                              void* d_out, int out_size)
{
    const float* X    = (const float*)d_in[0];
    const float* Win  = (const float*)d_in[1];
    const float* Wout = (const float*)d_in[2];
    const float* Wb   = (const float*)d_in[3];
    float* Y = (float*)d_out;

    cudaFuncSetAttribute(gemm3_f16,
                         cudaFuncAttributeMaxDynamicSharedMemorySize, GSMEM);

    split_kernel<<<(TOTG + 255) / 256, 256>>>(X, Win, Wout, Wb);
    gemm3_f16<<<dim3(MTOK / BM, NTOT / BN), 256, GSMEM>>>(X);
    finalize_kernel<<<MTOK / 4, 128>>>(Y);
}

// round 12
// speedup vs baseline: 1.3887x; 1.1215x over previous
#include <cuda_runtime.h>
#include <cuda_fp16.h>
#include <cstdint>

// Problem constants
#define B_    2
#define S_    512
#define D_    512
#define MTOK  1024          // B*S tokens
#define NTOT  1536          // w1 | w2 | w3
#define EPS_  1e-5f

// Static device scratch
__device__ float  g_P[MTOK * NTOT];     // w2|w3 projections (w1 region unused)
__device__ float4 g_W1R[MTOK][16];      // per-token partials: sum,sq,dot,sx
__device__ __half g_A0[MTOK * D_];      // X hi split
__device__ __half g_A1[MTOK * D_];      // X lo split
__device__ __half g_B0[NTOT * D_];      // W hi split, PERMUTED row order
__device__ __half g_B1[512 * D_];       // W lo split, w2 rows ONLY (compact)

// Column permutation: every 48-block = [32 w13-cols][16 w2-cols].
// Original concat: w1=[0,512) w2=[512,1024) w3=[1024,1536).
__device__ __forceinline__ int perm_to_orig(int p) {
    const int b = p / 48, r = p % 48;
    if (r < 32) { const int u = b * 32 + r; return (u < 512) ? u : u + 512; }
    return 512 + b * 16 + (r - 32);
}

// ---------------------------------------------------------------------------
// Kernel 0: split fp32 -> fp16 hi/lo. B-hi full permuted; B-lo only w2 rows.
// ---------------------------------------------------------------------------
#define XFL   (MTOK * D_)              // 524288 floats in X
#define TOTG  ((MTOK + NTOT) * D_ / 8) // 163840 groups of 8

__global__ __launch_bounds__(256) void split_kernel(
    const float* __restrict__ X,
    const float* __restrict__ Win,
    const float* __restrict__ Wout,
    const float* __restrict__ Wb)
{
    const int g = blockIdx.x * 256 + threadIdx.x;
    if (g >= TOTG) return;
    const int q = g * 8;

    const float* src;
    __half *d0, *d1 = nullptr;
    if (q < XFL) {
        src = X + q;
        d0 = g_A0 + q;  d1 = g_A1 + q;
    } else {
        const int wq = q - XFL;
        const int np = wq >> 9;            // permuted row
        const int k  = wq & (D_ - 1);
        const int o  = perm_to_orig(np);   // original concat col
        src = (o < D_ ? Win + o * D_
                      : (o < 2 * D_ ? Wout + (o - D_) * D_
                                    : Wb + (o - 2 * D_) * D_)) + k;
        d0 = g_B0 + wq;
        const int r48 = np % 48;
        if (r48 >= 32)                     // w2 row -> compact lo array
            d1 = g_B1 + ((np / 48) * 16 + (r48 - 32)) * D_ + k;
    }
    const float4 v0 = reinterpret_cast<const float4*>(src)[0];
    const float4 v1 = reinterpret_cast<const float4*>(src)[1];
    float f[8] = {v0.x, v0.y, v0.z, v0.w, v1.x, v1.y, v1.z, v1.w};
    __half hi[8], lo[8];
    #pragma unroll
    for (int i = 0; i < 8; ++i) {
        hi[i] = __float2half_rn(f[i]);
        lo[i] = __float2half_rn(f[i] - __half2float(hi[i]));
    }
    uint4 sh, sl;
    sh.x = *(uint32_t*)&hi[0]; sh.y = *(uint32_t*)&hi[2];
    sh.z = *(uint32_t*)&hi[4]; sh.w = *(uint32_t*)&hi[6];
    sl.x = *(uint32_t*)&lo[0]; sl.y = *(uint32_t*)&lo[2];
    sl.z = *(uint32_t*)&lo[4]; sl.w = *(uint32_t*)&lo[6];
    *reinterpret_cast<uint4*>(d0) = sh;
    if (d1) *reinterpret_cast<uint4*>(d1) = sl;
}

// ---------------------------------------------------------------------------
// Kernel 1: GEMM, mixed pass-count, 3-stage pipeline, ldmatrix fragment loads,
// fused w1 reduction. BM=128 BN=96 BK=32, grid 8x16 = 128 CTAs.
// ---------------------------------------------------------------------------
#define BM 128
#define BN 96
#define BK 32
#define KP 40
#define A_OFF   0
#define A1_OFF  (BM * KP)                    // 5120
#define B_OFF   (2 * BM * KP)                // 10240
#define B1_OFF  (2 * BM * KP + BN * KP)      // 14080 (compact: 32 rows)
#define STAGE_H (2 * BM * KP + BN * KP + 32 * KP)  // 15360 halves
#define NSTG    3
#define GSMEM   (NSTG * STAGE_H * 2)               // 92160 B

__device__ __forceinline__ void cp16(uint32_t smem, const void* gmem) {
    asm volatile("cp.async.cg.shared.global [%0], [%1], 16;\n"
                 :: "r"(smem), "l"(gmem));
}

__device__ __forceinline__ void ldsm_x4(uint32_t* r, uint32_t addr) {
    asm volatile("ldmatrix.sync.aligned.m8n8.x4.shared.b16 {%0,%1,%2,%3}, [%4];"
        : "=r"(r[0]), "=r"(r[1]), "=r"(r[2]), "=r"(r[3]) : "r"(addr));
}

__device__ __forceinline__ void mma_f16(float* c,
    uint32_t a0, uint32_t a1, uint32_t a2, uint32_t a3,
    uint32_t b0, uint32_t b1)
{
    asm volatile(
        "mma.sync.aligned.m16n8k16.row.col.f32.f16.f16.f32 "
        "{%0,%1,%2,%3}, {%4,%5,%6,%7}, {%8,%9}, {%0,%1,%2,%3};"
        : "+f"(c[0]), "+f"(c[1]), "+f"(c[2]), "+f"(c[3])
        : "r"(a0), "r"(a1), "r"(a2), "r"(a3), "r"(b0), "r"(b1));
}

__global__ __launch_bounds__(256, 1) void gemm3_f16(const float* __restrict__ X)
{
    extern __shared__ __half sm[];

    const int tid   = threadIdx.x;
    const int lane  = tid & 31;
    const int wid   = tid >> 5;
    const int warpM = wid >> 1;         // 0..3
    const int warpN = wid & 1;          // 0..1
    const int gID   = lane >> 2;        // 0..7
    const int tIG   = lane & 3;         // 0..3
    const int m0    = blockIdx.x * BM;
    const int by    = blockIdx.y;
    const int n0    = by * BN;          // permuted col base
    const int w2b   = by * 32;          // compact B1 row base

    const uint32_t sbase = (uint32_t)__cvta_generic_to_shared(sm);

    // ldmatrix per-thread address components (within a stage, in halves)
    const int rA  = warpM * 32 + (lane & 15);      // + i*16 rows
    const int cA  = (lane >> 4) * 8;               // + kk cols
    const int tB  = lane >> 3;                     // 0..3 tile id
    const int rBh = warpN * 48 + (tB >> 1) * 8 + (lane & 7);  // + p*16 rows
    const int rBl = warpN * 16 + (tB >> 1) * 8 + (lane & 7);
    const int cB  = (tB & 1) * 8;                  // + kk cols

    float acc[2][6][4];
    #pragma unroll
    for (int i = 0; i < 2; i++)
        #pragma unroll
        for (int j = 0; j < 6; j++)
            #pragma unroll
            for (int q = 0; q < 4; q++) acc[i][j][q] = 0.f;

    auto issue = [&](int t, int stg) {
        const int k0 = t * BK;
        const uint32_t st = sbase + (uint32_t)(stg * STAGE_H) * 2u;
        #pragma unroll
        for (int it = 0; it < 2; ++it) {
            const int c = tid + it * 256;
            const int r = c >> 2, qd = c & 3;
            const uint32_t so = (uint32_t)(r * KP + qd * 8) * 2u;
            cp16(st + A_OFF * 2u + so,  g_A0 + (m0 + r) * D_ + k0 + qd * 8);
            cp16(st + A1_OFF * 2u + so, g_A1 + (m0 + r) * D_ + k0 + qd * 8);
        }
        #pragma unroll
        for (int c = tid; c < 384; c += 256) {
            const int r = c >> 2, qd = c & 3;
            cp16(st + B_OFF * 2u + (uint32_t)(r * KP + qd * 8) * 2u,
                 g_B0 + (n0 + r) * D_ + k0 + qd * 8);
        }
        if (tid < 128) {                 // B1 compact: 32 rows x 4 chunks
            const int r = tid >> 2, qd = tid & 3;
            cp16(st + B1_OFF * 2u + (uint32_t)(r * KP + qd * 8) * 2u,
                 g_B1 + (w2b + r) * D_ + k0 + qd * 8);
        }
        asm volatile("cp.async.commit_group;");
    };

    auto compute = [&](int stg) {
        const uint32_t sst = sbase + (uint32_t)(stg * STAGE_H) * 2u;
        const uint32_t aA0 = sst + (uint32_t)(A_OFF  + rA * KP + cA) * 2u;
        const uint32_t aA1 = sst + (uint32_t)(A1_OFF + rA * KP + cA) * 2u;
        const uint32_t aBh = sst + (uint32_t)(B_OFF  + rBh * KP + cB) * 2u;
        const uint32_t aBl = sst + (uint32_t)(B1_OFF + rBl * KP + cB) * 2u;
        #pragma unroll
        for (int kk = 0; kk < BK; kk += 16) {
            const uint32_t ko = (uint32_t)(kk * 2);
            uint32_t ah[2][4], al[2][4], bh[6][2], bl[2][2];
            ldsm_x4(ah[0], aA0 + ko);
            ldsm_x4(ah[1], aA0 + ko + (uint32_t)(16 * KP * 2));
            ldsm_x4(al[0], aA1 + ko);
            ldsm_x4(al[1], aA1 + ko + (uint32_t)(16 * KP * 2));
            #pragma unroll
            for (int p = 0; p < 3; ++p) {
                uint32_t r[4];
                ldsm_x4(r, aBh + ko + (uint32_t)(p * 16 * KP * 2));
                bh[2 * p][0] = r[0];  bh[2 * p][1] = r[1];
                bh[2 * p + 1][0] = r[2];  bh[2 * p + 1][1] = r[3];
            }
            {
                uint32_t r[4];
                ldsm_x4(r, aBl + ko);
                bl[0][0] = r[0];  bl[0][1] = r[1];
                bl[1][0] = r[2];  bl[1][1] = r[3];
            }
            // w2 atoms: 3-pass exact
            #pragma unroll
            for (int i = 0; i < 2; ++i)
                #pragma unroll
                for (int jj = 0; jj < 2; ++jj)
                    mma_f16(acc[i][4 + jj], ah[i][0], ah[i][1], ah[i][2], ah[i][3],
                            bl[jj][0], bl[jj][1]);
            #pragma unroll
            for (int i = 0; i < 2; ++i)
                #pragma unroll
                for (int jj = 0; jj < 2; ++jj)
                    mma_f16(acc[i][4 + jj], al[i][0], al[i][1], al[i][2], al[i][3],
                            bh[4 + jj][0], bh[4 + jj][1]);
            // all atoms: ah*bh
            #pragma unroll
            for (int i = 0; i < 2; ++i)
                #pragma unroll
                for (int j = 0; j < 6; ++j)
                    mma_f16(acc[i][j], ah[i][0], ah[i][1], ah[i][2], ah[i][3],
                            bh[j][0], bh[j][1]);
        }
    };

    constexpr int T = D_ / BK;   // 16
    issue(0, 0);
    issue(1, 1);
    #pragma unroll 1
    for (int t = 0; t < T; ++t) {
        if (t + 1 < T) asm volatile("cp.async.wait_group 1;");
        else           asm volatile("cp.async.wait_group 0;");
        __syncthreads();
        compute(t % NSTG);
        // NSTG=3: issue(t+2) writes stage (t-1)%3, finished by ALL warps
        // before this iteration's barrier -> no second __syncthreads needed.
        if (t + 2 < T) issue(t + 2, (t + 2) % NSTG);
    }

    // -------- Epilogue --------
    if (by < 8) {
        // w13 atoms are w1 columns: reduce in-register, write partials.
        const int ub = (2 * by + warpN) * 32;       // orig col base (32 cols)
        #pragma unroll
        for (int i = 0; i < 2; ++i)
            #pragma unroll
            for (int half = 0; half < 2; ++half) {
                const int row = m0 + warpM * 32 + i * 16 + half * 8 + gID;
                float s = 0.f, qd = 0.f, dx = 0.f, sx = 0.f;
                #pragma unroll
                for (int j = 0; j < 4; ++j) {
                    const float w1a = acc[i][j][half * 2 + 0];
                    const float w1b = acc[i][j][half * 2 + 1];
                    const float2 xv = *reinterpret_cast<const float2*>(
                        &X[row * D_ + ub + j * 8 + 2 * tIG]);
                    s  += w1a + w1b;
                    qd += w1a * w1a + w1b * w1b;
                    dx += w1a * xv.x + w1b * xv.y;
                    sx += xv.x + xv.y;
                }
                #pragma unroll
                for (int o = 1; o < 4; o <<= 1) {
                    s  += __shfl_xor_sync(0xffffffffu, s,  o);
                    qd += __shfl_xor_sync(0xffffffffu, qd, o);
                    dx += __shfl_xor_sync(0xffffffffu, dx, o);
                    sx += __shfl_xor_sync(0xffffffffu, sx, o);
                }
                if (tIG == 0)
                    g_W1R[row][by * 2 + warpN] = make_float4(s, qd, dx, sx);
            }
    } else {
        // w13 atoms are w3 columns: store to g_P.
        #pragma unroll
        for (int i = 0; i < 2; ++i) {
            const int r = m0 + warpM * 32 + i * 16 + gID;
            #pragma unroll
            for (int j = 0; j < 4; ++j) {
                const int cp = n0 + warpN * 48 + j * 8 + 2 * tIG;
                const int co = perm_to_orig(cp);
                *reinterpret_cast<float2*>(&g_P[r * NTOT + co]) =
                    make_float2(acc[i][j][0], acc[i][j][1]);
                *reinterpret_cast<float2*>(&g_P[(r + 8) * NTOT + co]) =
                    make_float2(acc[i][j][2], acc[i][j][3]);
            }
        }
    }
    // w2 atoms: store (all CTAs)
    #pragma unroll
    for (int i = 0; i < 2; ++i) {
        const int r = m0 + warpM * 32 + i * 16 + gID;
        #pragma unroll
        for (int j = 4; j < 6; ++j) {
            const int cp = n0 + warpN * 48 + j * 8 + 2 * tIG;
            const int co = perm_to_orig(cp);
            *reinterpret_cast<float2*>(&g_P[r * NTOT + co]) =
                make_float2(acc[i][j][0], acc[i][j][1]);
            *reinterpret_cast<float2*>(&g_P[(r + 8) * NTOT + co]) =
                make_float2(acc[i][j][2], acc[i][j][3]);
        }
    }
}

// ---------------------------------------------------------------------------
// Kernel 2: finalize, warp-per-token. Reads only w2, w3 + partials.
// ---------------------------------------------------------------------------
__global__ __launch_bounds__(128) void finalize_kernel(float* __restrict__ Y)
{
    const int warp = threadIdx.x >> 5;
    const int lane = threadIdx.x & 31;
    const int m    = blockIdx.x * 4 + warp;
    const float* p = g_P + m * NTOT;

    // Gather the 16 w1 partials (lanes 0..15), reduce across warp.
    float4 pp = (lane < 16) ? g_W1R[m][lane] : make_float4(0.f, 0.f, 0.f, 0.f);
    #pragma unroll
    for (int o = 1; o < 32; o <<= 1) {
        pp.x += __shfl_xor_sync(0xffffffffu, pp.x, o);
        pp.y += __shfl_xor_sync(0xffffffffu, pp.y, o);
        pp.z += __shfl_xor_sync(0xffffffffu, pp.z, o);
        pp.w += __shfl_xor_sync(0xffffffffu, pp.w, o);
    }
    const float sw1 = pp.x, sw1q = pp.y, sw1x = pp.z, sx = pp.w;

    float4 v[4], c[4];
    #pragma unroll
    for (int q = 0; q < 4; ++q) {
        const int off = q * 128 + lane * 4;
        v[q] = *reinterpret_cast<const float4*>(&p[D_ + off]);       // w2
        c[q] = *reinterpret_cast<const float4*>(&p[2 * D_ + off]);   // w3
    }
    float sw3 = 0.f, sw3q = 0.f;
    #pragma unroll
    for (int q = 0; q < 4; ++q) {
        sw3  += (c[q].x + c[q].y) + (c[q].z + c[q].w);
        sw3q += (c[q].x * c[q].x + c[q].y * c[q].y)
              + (c[q].z * c[q].z + c[q].w * c[q].w);
    }
    #pragma unroll
    for (int o = 1; o < 32; o <<= 1) {
        sw3  += __shfl_xor_sync(0xffffffffu, sw3,  o);
        sw3q += __shfl_xor_sync(0xffffffffu, sw3q, o);
    }

    const float invD = 1.0f / (float)D_;
    const float mu1  = sw1 * invD;
    const float var1 = fmaxf(sw1q * invD - mu1 * mu1, 0.f);
    const float s    = sw1x - mu1 * sx;
    const float mu3  = sw3 * invD;
    const float var3 = fmaxf(sw3q * invD - mu3 * mu3, 0.f);
    const float inv3 = rsqrtf(var3 + EPS_);

    #pragma unroll
    for (int q = 0; q < 4; ++q) {
        float4 out;
        out.x = v[q].x * s * rsqrtf(v[q].x * v[q].x * var1 + EPS_)
              + (c[q].x - mu3) * inv3;
        out.y = v[q].y * s * rsqrtf(v[q].y * v[q].y * var1 + EPS_)
              + (c[q].y - mu3) * inv3;
        out.z = v[q].z * s * rsqrtf(v[q].z * v[q].z * var1 + EPS_)
              + (c[q].z - mu3) * inv3;
        out.w = v[q].w * s * rsqrtf(v[q].w * v[q].w * var1 + EPS_)
              + (c[q].w - mu3) * inv3;
        *reinterpret_cast<float4*>(&Y[m * D_ + q * 128 + lane * 4]) = out;
    }
}

// ---------------------------------------------------------------------------
extern "C" void kernel_launch(void* const* d_in, const int* in_sizes, int n_in,
                              void* d_out, int out_size)
{
    const float* X    = (const float*)d_in[0];
    const float* Win  = (const float*)d_in[1];
    const float* Wout = (const float*)d_in[2];
    const float* Wb   = (const float*)d_in[3];
    float* Y = (float*)d_out;

    cudaFuncSetAttribute(gemm3_f16,
                         cudaFuncAttributeMaxDynamicSharedMemorySize, GSMEM);

    split_kernel<<<(TOTG + 255) / 256, 256>>>(X, Win, Wout, Wb);
    gemm3_f16<<<dim3(MTOK / BM, NTOT / BN), 256, GSMEM>>>(X);
    finalize_kernel<<<MTOK / 4, 128>>>(Y);
}